// round 1
// baseline (speedup 1.0000x reference)
#include <cuda_runtime.h>
#include <cuda_bf16.h>
#include <float.h>

// ---------------- problem constants ----------------
#define BATCH     2
#define SEQ       2048
#define DMODEL    1024
#define NHEADS    16
#define HDIM      64
#define WINDOW    64
#define GTOK      4
#define RTOK      32
#define NROWS     (BATCH*SEQ)      // 4096
#define MAXC      112              // 65 + 8 + 32 = 105, padded
#define NEGF      (-1000000000.0f)
#define LNEPS     1e-5f

// ---------------- scratch (static device memory; no allocations) ----------------
__device__ float g_xn  [NROWS * DMODEL];      // layernorm output
__device__ float g_qkv [NROWS * 3 * DMODEL];  // fused qkv projection
__device__ float g_attn[NROWS * DMODEL];      // attention output (pre out-proj)
__device__ int   g_cols[SEQ * MAXC];
__device__ float g_pen [SEQ * MAXC];
__device__ int   g_ncols[SEQ];

// ---------------- layernorm: one block per row ----------------
__global__ __launch_bounds__(256) void ln_kernel(const float* __restrict__ x,
                                                 const float* __restrict__ gamma,
                                                 const float* __restrict__ beta) {
    int row = blockIdx.x;
    const float4* xr = (const float4*)(x + (size_t)row * DMODEL);
    float4*       ot = (float4*)(g_xn + (size_t)row * DMODEL);
    int t = threadIdx.x;               // 256 threads * 4 = 1024
    float4 v = xr[t];

    __shared__ float sh[8];
    __shared__ float bc;
    int lane = t & 31, warp = t >> 5;

    // mean
    float s = v.x + v.y + v.z + v.w;
    #pragma unroll
    for (int o = 16; o; o >>= 1) s += __shfl_down_sync(0xffffffffu, s, o);
    if (lane == 0) sh[warp] = s;
    __syncthreads();
    if (t == 0) {
        float tot = 0;
        #pragma unroll
        for (int i = 0; i < 8; i++) tot += sh[i];
        bc = tot * (1.0f / DMODEL);
    }
    __syncthreads();
    float mu = bc;
    __syncthreads();

    // variance (two-pass)
    float dx = v.x - mu, dy = v.y - mu, dz = v.z - mu, dw = v.w - mu;
    float sq = dx*dx + dy*dy + dz*dz + dw*dw;
    #pragma unroll
    for (int o = 16; o; o >>= 1) sq += __shfl_down_sync(0xffffffffu, sq, o);
    if (lane == 0) sh[warp] = sq;
    __syncthreads();
    if (t == 0) {
        float tot = 0;
        #pragma unroll
        for (int i = 0; i < 8; i++) tot += sh[i];
        bc = rsqrtf(tot * (1.0f / DMODEL) + LNEPS);
    }
    __syncthreads();
    float inv = bc;

    const float4 g = ((const float4*)gamma)[t];
    const float4 b = ((const float4*)beta)[t];
    float4 r;
    r.x = dx * inv * g.x + b.x;
    r.y = dy * inv * g.y + b.y;
    r.z = dz * inv * g.z + b.z;
    r.w = dw * inv * g.w + b.w;
    ot[t] = r;
}

// ---------------- per-row sparse column list + penalties ----------------
__global__ void build_cols(const int* __restrict__ rand_idx) {
    int q = blockIdx.x * blockDim.x + threadIdx.x;
    if (q >= SEQ) return;
    int*   cols = g_cols + q * MAXC;
    float* pen  = g_pen  + q * MAXC;
    const int* ri = rand_idx + q * RTOK;

    int lo = q - WINDOW; if (lo < 0) lo = 0;
    int n = 0;
    for (int c = lo; c <= q; c++) cols[n++] = c;     // local window (always active)
    int wend = n;                                     // appended region starts here

    // global columns not inside the window
    #pragma unroll
    for (int gi = 0; gi < 2 * GTOK; gi++) {
        int gc = (gi < GTOK) ? gi : (SEQ - 2 * GTOK + gi);
        if (gc <= q && gc < lo) cols[n++] = gc;
    }
    // random columns (causal, deduped vs window and appended entries)
    for (int j = 0; j < RTOK; j++) {
        int c = ri[j];
        if (c > q || c >= lo) continue;               // acausal or already in window
        bool dup = false;
        for (int m = wend; m < n; m++) if (cols[m] == c) { dup = true; break; }
        if (!dup) cols[n++] = c;
    }
    g_ncols[q] = n;

    // penalty = (3 - s) * NEG, s = local + global + random membership
    for (int i = 0; i < n; i++) {
        int c = cols[i];
        int s = (c >= lo) ? 1 : 0;                    // local (c<=q guaranteed)
        if (c < GTOK || c >= SEQ - GTOK) s++;         // global
        for (int j = 0; j < RTOK; j++) if (ri[j] == c) { s++; break; }
        pen[i] = (float)(3 - s) * NEGF;
    }
}

// ---------------- fp32 SGEMM: C[M,N] = A[M,K] @ B[K,N] (+ residual) ----------------
// 128x128 tile, BK=16, 256 threads, 8x8 per-thread microtile.
template<int RES>
__global__ __launch_bounds__(256) void sgemm128(const float* __restrict__ A,
                                                const float* __restrict__ B,
                                                float* __restrict__ C,
                                                const float* __restrict__ res,
                                                int M, int N, int K) {
    __shared__ float As[16][128];
    __shared__ float Bs[16][128];

    int tid = threadIdx.x;
    int tx = tid & 15, ty = tid >> 4;          // 16 x 16 thread grid
    int brow = blockIdx.y * 128;
    int bcol = blockIdx.x * 128;

    float acc[8][8];
    #pragma unroll
    for (int i = 0; i < 8; i++)
        #pragma unroll
        for (int j = 0; j < 8; j++) acc[i][j] = 0.0f;

    int aRow = tid >> 2;             // 0..63
    int aCol = (tid & 3) << 2;       // 0,4,8,12
    int bRow = tid >> 5;             // 0..7
    int bCol = (tid & 31) << 2;      // 0..124

    for (int k0 = 0; k0 < K; k0 += 16) {
        #pragma unroll
        for (int r = 0; r < 2; r++) {
            float4 a = *(const float4*)(A + (size_t)(brow + aRow + r * 64) * K + k0 + aCol);
            As[aCol + 0][aRow + r * 64] = a.x;
            As[aCol + 1][aRow + r * 64] = a.y;
            As[aCol + 2][aRow + r * 64] = a.z;
            As[aCol + 3][aRow + r * 64] = a.w;
        }
        #pragma unroll
        for (int r = 0; r < 2; r++) {
            float4 bv = *(const float4*)(B + (size_t)(k0 + bRow + r * 8) * N + bcol + bCol);
            *(float4*)&Bs[bRow + r * 8][bCol] = bv;
        }
        __syncthreads();

        #pragma unroll
        for (int kk = 0; kk < 16; kk++) {
            float ra[8], rb[8];
            *(float4*)&ra[0] = *(const float4*)&As[kk][ty * 8];
            *(float4*)&ra[4] = *(const float4*)&As[kk][ty * 8 + 4];
            *(float4*)&rb[0] = *(const float4*)&Bs[kk][tx * 8];
            *(float4*)&rb[4] = *(const float4*)&Bs[kk][tx * 8 + 4];
            #pragma unroll
            for (int i = 0; i < 8; i++)
                #pragma unroll
                for (int j = 0; j < 8; j++)
                    acc[i][j] = fmaf(ra[i], rb[j], acc[i][j]);
        }
        __syncthreads();
    }

    #pragma unroll
    for (int i = 0; i < 8; i++) {
        size_t roff = (size_t)(brow + ty * 8 + i) * N + bcol + tx * 8;
        #pragma unroll
        for (int j = 0; j < 8; j += 4) {
            float4 v = make_float4(acc[i][j], acc[i][j+1], acc[i][j+2], acc[i][j+3]);
            if (RES) {
                float4 rr = *(const float4*)(res + roff + j);
                v.x += rr.x; v.y += rr.y; v.z += rr.z; v.w += rr.w;
            }
            *(float4*)(C + roff + j) = v;
        }
    }
}

// ---------------- sparse attention: one block per (b,h,q) ----------------
__global__ __launch_bounds__(128) void attn_sparse() {
    int q = blockIdx.x, h = blockIdx.y, b = blockIdx.z;
    int t = threadIdx.x;
    int nc = g_ncols[q];

    __shared__ float qs[HDIM];
    __shared__ float wgt[MAXC];
    __shared__ int   scols[MAXC];
    __shared__ float sred[128];

    const float* base = g_qkv + (size_t)(b * SEQ + q) * (3 * DMODEL);
    if (t < HDIM) qs[t] = base[h * HDIM + t];
    if (t < nc)   scols[t] = g_cols[q * MAXC + t];
    __syncthreads();

    // logits: one warp per column
    int warp = t >> 5, lane = t & 31;
    for (int i = warp; i < nc; i += 4) {
        int c = scols[i];
        const float* kr = g_qkv + (size_t)(b * SEQ + c) * (3 * DMODEL) + DMODEL + h * HDIM;
        float p = qs[lane] * kr[lane] + qs[lane + 32] * kr[lane + 32];
        #pragma unroll
        for (int o = 16; o; o >>= 1) p += __shfl_down_sync(0xffffffffu, p, o);
        if (lane == 0)
            wgt[i] = 3.0f * (p * 0.125f) + g_pen[q * MAXC + i];   // matches reference f32 arithmetic
    }
    __syncthreads();

    // softmax max
    float lm = -FLT_MAX;
    for (int i = t; i < nc; i += 128) lm = fmaxf(lm, wgt[i]);
    sred[t] = lm; __syncthreads();
    #pragma unroll
    for (int s2 = 64; s2; s2 >>= 1) {
        if (t < s2) sred[t] = fmaxf(sred[t], sred[t + s2]);
        __syncthreads();
    }
    float mx = sred[0];
    __syncthreads();

    // exp + sum (expf(-1e9) underflows to exactly 0, matching the reference tiers)
    float ls = 0.0f;
    for (int i = t; i < nc; i += 128) {
        float e = expf(wgt[i] - mx);
        wgt[i] = e;
        ls += e;
    }
    sred[t] = ls; __syncthreads();
    #pragma unroll
    for (int s2 = 64; s2; s2 >>= 1) {
        if (t < s2) sred[t] += sred[t + s2];
        __syncthreads();
    }
    float inv = 1.0f / sred[0];
    __syncthreads();

    // weighted sum of V rows (two halves of the block split the columns)
    int half = t >> 6, d = t & 63;
    float acc = 0.0f;
    for (int i = half; i < nc; i += 2) {
        int c = scols[i];
        acc += wgt[i] * g_qkv[(size_t)(b * SEQ + c) * (3 * DMODEL) + 2 * DMODEL + h * HDIM + d];
    }
    sred[t] = acc; __syncthreads();
    if (half == 0) {
        float o = (acc + sred[64 + d]) * inv;
        g_attn[(size_t)(b * SEQ + q) * DMODEL + h * HDIM + d] = o;
    }
}

// ---------------- launch ----------------
extern "C" void kernel_launch(void* const* d_in, const int* in_sizes, int n_in,
                              void* d_out, int out_size) {
    const float* x        = (const float*)d_in[0];
    const float* w_qkv    = (const float*)d_in[1];
    const float* w_out    = (const float*)d_in[2];
    const float* ln_gamma = (const float*)d_in[3];
    const float* ln_beta  = (const float*)d_in[4];
    const int*   rand_idx = (const int*)d_in[5];
    float* out = (float*)d_out;

    void *p_xn, *p_qkv, *p_attn;
    cudaGetSymbolAddress(&p_xn,   g_xn);
    cudaGetSymbolAddress(&p_qkv,  g_qkv);
    cudaGetSymbolAddress(&p_attn, g_attn);

    // 1) layernorm
    ln_kernel<<<NROWS, 256>>>(x, ln_gamma, ln_beta);

    // 2) sparse column lists (b/h independent)
    build_cols<<<(SEQ + 127) / 128, 128>>>(rand_idx);

    // 3) fused QKV projection: [4096,1024] @ [1024,3072]
    sgemm128<0><<<dim3((3 * DMODEL) / 128, NROWS / 128), 256>>>(
        (const float*)p_xn, w_qkv, (float*)p_qkv, nullptr,
        NROWS, 3 * DMODEL, DMODEL);

    // 4) sparse attention
    attn_sparse<<<dim3(SEQ, NHEADS, BATCH), 128>>>();

    // 5) output projection + residual: [4096,1024] @ [1024,1024] + x
    sgemm128<1><<<dim3(DMODEL / 128, NROWS / 128), 256>>>(
        (const float*)p_attn, w_out, out, x,
        NROWS, DMODEL, DMODEL);
}

// round 6
// speedup vs baseline: 1.5044x; 1.5044x over previous
#include <cuda_runtime.h>
#include <cuda_bf16.h>
#include <float.h>
#include <stdint.h>

// ---------------- problem constants ----------------
#define BATCH     2
#define SEQ       2048
#define DMODEL    1024
#define NHEADS    16
#define HDIM      64
#define WINDOW    64
#define GTOK      4
#define RTOK      32
#define NROWS     (BATCH*SEQ)      // 4096
#define MAXC      112
#define NEGF      (-1000000000.0f)
#define LNEPS     1e-5f
#define KK2       (3*DMODEL)       // 3072: [hi|hi|lo] x [hi;lo;hi] concat-K
#define NCH       (KK2/64)         // 48 k-chunks of 64 bf16

// ---------------- scratch (static device memory) ----------------
__device__ float        g_xn  [NROWS * DMODEL];
__device__ float        g_qkv [NROWS * 3 * DMODEL];
__device__ float        g_attn[NROWS * DMODEL];
__device__ __nv_bfloat16 g_a2 [NROWS * KK2];          // split activations (reused)
__device__ __nv_bfloat16 g_wq2[3*DMODEL * KK2];       // w_qkv^T split  [N=3072][K'=3072]
__device__ __nv_bfloat16 g_wo2[DMODEL   * KK2];       // w_out^T split  [N=1024][K'=3072]
__device__ int   g_cols[SEQ * MAXC];
__device__ float g_pen [SEQ * MAXC];
__device__ int   g_ncols[SEQ];

// ---------------- PTX helpers (sm_80-era only; no tcgen05 on this target) ----
__device__ __forceinline__ uint32_t smem_u32(const void* p) {
    uint32_t a;
    asm("{ .reg .u64 t; cvta.to.shared.u64 t, %1; cvt.u32.u64 %0, t; }" : "=r"(a) : "l"(p));
    return a;
}
__device__ __forceinline__ void cpasync16(uint32_t dst, const void* src) {
    asm volatile("cp.async.cg.shared.global [%0], [%1], 16;" :: "r"(dst), "l"(src));
}
__device__ __forceinline__ void ldm_x4(uint32_t* r, uint32_t addr) {
    asm volatile("ldmatrix.sync.aligned.m8n8.x4.shared.b16 {%0,%1,%2,%3}, [%4];"
                 : "=r"(r[0]), "=r"(r[1]), "=r"(r[2]), "=r"(r[3]) : "r"(addr));
}
__device__ __forceinline__ void mma16816(float* c, const uint32_t* a,
                                         uint32_t b0, uint32_t b1) {
    asm volatile("mma.sync.aligned.m16n8k16.row.col.f32.bf16.bf16.f32 "
                 "{%0,%1,%2,%3}, {%4,%5,%6,%7}, {%8,%9}, {%0,%1,%2,%3};"
                 : "+f"(c[0]), "+f"(c[1]), "+f"(c[2]), "+f"(c[3])
                 : "r"(a[0]), "r"(a[1]), "r"(a[2]), "r"(a[3]), "r"(b0), "r"(b1));
}
#define SMEM_SWIZZLE_128B(o) ((o) ^ (((o) >> 3) & 0x70))

// ---------------- layernorm: one block per row ----------------
__global__ __launch_bounds__(256) void ln_kernel(const float* __restrict__ x,
                                                 const float* __restrict__ gamma,
                                                 const float* __restrict__ beta) {
    int row = blockIdx.x;
    const float4* xr = (const float4*)(x + (size_t)row * DMODEL);
    float4*       ot = (float4*)(g_xn + (size_t)row * DMODEL);
    int t = threadIdx.x;
    float4 v = xr[t];

    __shared__ float sh[8];
    __shared__ float bc;
    int lane = t & 31, warp = t >> 5;

    float s = v.x + v.y + v.z + v.w;
    #pragma unroll
    for (int o = 16; o; o >>= 1) s += __shfl_down_sync(0xffffffffu, s, o);
    if (lane == 0) sh[warp] = s;
    __syncthreads();
    if (t == 0) {
        float tot = 0;
        #pragma unroll
        for (int i = 0; i < 8; i++) tot += sh[i];
        bc = tot * (1.0f / DMODEL);
    }
    __syncthreads();
    float mu = bc;
    __syncthreads();

    float dx = v.x - mu, dy = v.y - mu, dz = v.z - mu, dw = v.w - mu;
    float sq = dx*dx + dy*dy + dz*dz + dw*dw;
    #pragma unroll
    for (int o = 16; o; o >>= 1) sq += __shfl_down_sync(0xffffffffu, sq, o);
    if (lane == 0) sh[warp] = sq;
    __syncthreads();
    if (t == 0) {
        float tot = 0;
        #pragma unroll
        for (int i = 0; i < 8; i++) tot += sh[i];
        bc = rsqrtf(tot * (1.0f / DMODEL) + LNEPS);
    }
    __syncthreads();
    float inv = bc;

    const float4 g = ((const float4*)gamma)[t];
    const float4 b = ((const float4*)beta)[t];
    float4 r;
    r.x = dx * inv * g.x + b.x;
    r.y = dy * inv * g.y + b.y;
    r.z = dz * inv * g.z + b.z;
    r.w = dw * inv * g.w + b.w;
    ot[t] = r;
}

// ---------------- per-row sparse column list + penalties ----------------
__global__ void build_cols(const int* __restrict__ rand_idx) {
    int q = blockIdx.x * blockDim.x + threadIdx.x;
    if (q >= SEQ) return;
    int*   cols = g_cols + q * MAXC;
    float* pen  = g_pen  + q * MAXC;
    const int* ri = rand_idx + q * RTOK;

    int lo = q - WINDOW; if (lo < 0) lo = 0;
    int n = 0;
    for (int c = lo; c <= q; c++) cols[n++] = c;
    int wend = n;

    #pragma unroll
    for (int gi = 0; gi < 2 * GTOK; gi++) {
        int gc = (gi < GTOK) ? gi : (SEQ - 2 * GTOK + gi);
        if (gc <= q && gc < lo) cols[n++] = gc;
    }
    for (int j = 0; j < RTOK; j++) {
        int c = ri[j];
        if (c > q || c >= lo) continue;
        bool dup = false;
        for (int m = wend; m < n; m++) if (cols[m] == c) { dup = true; break; }
        if (!dup) cols[n++] = c;
    }
    g_ncols[q] = n;

    for (int i = 0; i < n; i++) {
        int c = cols[i];
        int s = (c >= lo) ? 1 : 0;
        if (c < GTOK || c >= SEQ - GTOK) s++;
        for (int j = 0; j < RTOK; j++) if (ri[j] == c) { s++; break; }
        pen[i] = (float)(3 - s) * NEGF;
    }
}

// ---------------- bf16 split conversion: activations ----------------
// src [rows,1024] f32 -> dst [rows, 3072] bf16 as [hi | hi | lo]
__global__ __launch_bounds__(256) void conv_act(const float* __restrict__ src,
                                                __nv_bfloat16* __restrict__ dst,
                                                int total) {
    int idx = blockIdx.x * 256 + threadIdx.x;
    if (idx >= total) return;
    float f = src[idx];
    __nv_bfloat16 hi = __float2bfloat16(f);
    __nv_bfloat16 lo = __float2bfloat16(f - __bfloat162float(hi));
    int row = idx >> 10, col = idx & 1023;
    size_t b = (size_t)row * KK2;
    dst[b + col] = hi;
    dst[b + DMODEL + col] = hi;
    dst[b + 2 * DMODEL + col] = lo;
}

// ---------------- bf16 split + transpose: weights ----------------
// w [1024, Nw] f32 -> wt2 [Nw, 3072] bf16 as rows n: [hi(w[:,n]) | lo | hi]
__global__ __launch_bounds__(256) void conv_w(const float* __restrict__ w,
                                              __nv_bfloat16* __restrict__ wt2,
                                              int Nw) {
    __shared__ float t[32][33];
    int tx = threadIdx.x, ty = threadIdx.y;       // blockDim (32,8)
    int n0 = blockIdx.x * 32, k0 = blockIdx.y * 32;
    #pragma unroll
    for (int r = 0; r < 4; r++)
        t[ty + r * 8][tx] = w[(size_t)(k0 + ty + r * 8) * Nw + n0 + tx];
    __syncthreads();
    #pragma unroll
    for (int r = 0; r < 4; r++) {
        int n = n0 + ty + r * 8;
        int k = k0 + tx;
        float f = t[tx][ty + r * 8];
        __nv_bfloat16 hi = __float2bfloat16(f);
        __nv_bfloat16 lo = __float2bfloat16(f - __bfloat162float(hi));
        size_t b = (size_t)n * KK2;
        wt2[b + k] = hi;
        wt2[b + DMODEL + k] = lo;
        wt2[b + 2 * DMODEL + k] = hi;
    }
}

// ---------------- bf16 HMMA GEMM: C[M,N] = A2[M,K'] @ Bt[N,K']^T (+res) --------
// 128x128 block tile, BK=64, 256 threads (8 warps, 2x4), warp tile 64x32.
// 4-stage cp.async pipeline, SW128-swizzled SMEM, ldmatrix + mma.sync m16n8k16.
#define GSTAGE 32768                     // A 16KB + B 16KB per chunk
#define GSMEM  (4 * GSTAGE)

template<int RES>
__global__ __launch_bounds__(256, 1) void gemm_mma(const __nv_bfloat16* __restrict__ A,
                                                   const __nv_bfloat16* __restrict__ Bt,
                                                   float* __restrict__ C,
                                                   const float* __restrict__ res,
                                                   int N) {
    extern __shared__ char smem[];
    uint32_t sb = smem_u32(smem);
    const int tid = threadIdx.x, wid = tid >> 5, lid = tid & 31;
    const int brow = blockIdx.y * 128, bcol = blockIdx.x * 128;
    const int wm = wid & 1, wn = wid >> 1;            // warp tile: rows wm*64, cols wn*32

    // cp.async issue of k-chunk c into stage c&3
    auto issue = [&](int c) {
        uint32_t abase = sb + (c & 3) * GSTAGE;
        uint32_t bbase = abase + 16384;
        int k0 = c * 64;
        #pragma unroll
        for (int i = 0; i < 4; i++) {
            int ca = tid + i * 256;
            int row = ca >> 3, seg = ca & 7;
            uint32_t off = SMEM_SWIZZLE_128B((uint32_t)(row * 128 + seg * 16));
            cpasync16(abase + off, A  + (size_t)(brow + row) * KK2 + k0 + seg * 8);
            cpasync16(bbase + off, Bt + (size_t)(bcol + row) * KK2 + k0 + seg * 8);
        }
        asm volatile("cp.async.commit_group;");
    };

    float acc[4][4][4];
    #pragma unroll
    for (int i = 0; i < 4; i++)
        #pragma unroll
        for (int j = 0; j < 4; j++)
            #pragma unroll
            for (int k = 0; k < 4; k++) acc[i][j][k] = 0.0f;

    // ldmatrix per-lane geometry (swizzle reduces to kb ^ ((row&7)<<4))
    const int xa   = (lid & 7) << 4;                  // same xor mask for A and B
    const int arow = wm * 64 + (lid & 15);            // + mt*16
    const int akhi = (lid >> 4) * 16;                 // byte offset of k-half
    const int bnrow = wn * 32 + (lid & 7) + ((lid >> 4) << 3);  // + nt2*16
    const int bkhi  = ((lid >> 3) & 1) * 16;

    issue(0); issue(1); issue(2); issue(3);

    for (int c = 0; c < NCH; c++) {
        int pend = NCH - 1 - c;
        if (pend >= 3)      asm volatile("cp.async.wait_group 3;" ::: "memory");
        else if (pend == 2) asm volatile("cp.async.wait_group 2;" ::: "memory");
        else if (pend == 1) asm volatile("cp.async.wait_group 1;" ::: "memory");
        else                asm volatile("cp.async.wait_group 0;" ::: "memory");
        __syncthreads();

        uint32_t abase = sb + (c & 3) * GSTAGE;
        uint32_t bbase = abase + 16384;

        #pragma unroll
        for (int ks = 0; ks < 4; ks++) {
            uint32_t a[4][4], b[2][4];
            int kb = ks * 32;
            #pragma unroll
            for (int mt = 0; mt < 4; mt++)
                ldm_x4(a[mt], abase + (arow + mt * 16) * 128 + ((kb + akhi) ^ xa));
            #pragma unroll
            for (int nt2 = 0; nt2 < 2; nt2++)
                ldm_x4(b[nt2], bbase + (bnrow + nt2 * 16) * 128 + ((kb + bkhi) ^ xa));
            #pragma unroll
            for (int mt = 0; mt < 4; mt++)
                #pragma unroll
                for (int nt = 0; nt < 4; nt++)
                    mma16816(acc[mt][nt], a[mt],
                             b[nt >> 1][(nt & 1) * 2], b[nt >> 1][(nt & 1) * 2 + 1]);
        }
        __syncthreads();
        if (c + 4 < NCH) issue(c + 4);
    }

    // epilogue
    const int g = lid >> 2, tg = lid & 3;
    #pragma unroll
    for (int mt = 0; mt < 4; mt++) {
        int r0 = brow + wm * 64 + mt * 16 + g;
        #pragma unroll
        for (int nt = 0; nt < 4; nt++) {
            int cI = bcol + wn * 32 + nt * 8 + tg * 2;
            float2 v0 = make_float2(acc[mt][nt][0], acc[mt][nt][1]);
            float2 v1 = make_float2(acc[mt][nt][2], acc[mt][nt][3]);
            if (RES) {
                float2 r0v = *(const float2*)(res + (size_t)r0 * N + cI);
                float2 r1v = *(const float2*)(res + (size_t)(r0 + 8) * N + cI);
                v0.x += r0v.x; v0.y += r0v.y;
                v1.x += r1v.x; v1.y += r1v.y;
            }
            *(float2*)(C + (size_t)r0 * N + cI) = v0;
            *(float2*)(C + (size_t)(r0 + 8) * N + cI) = v1;
        }
    }
}

// ---------------- sparse attention: one block per (b,h,q) ----------------
__global__ __launch_bounds__(128) void attn_sparse() {
    int q = blockIdx.x, h = blockIdx.y, b = blockIdx.z;
    int t = threadIdx.x;
    int nc = g_ncols[q];

    __shared__ float qs[HDIM];
    __shared__ float wgt[MAXC];
    __shared__ int   scols[MAXC];
    __shared__ float sred[128];

    const float* base = g_qkv + (size_t)(b * SEQ + q) * (3 * DMODEL);
    if (t < HDIM) qs[t] = base[h * HDIM + t];
    if (t < nc)   scols[t] = g_cols[q * MAXC + t];
    __syncthreads();

    int warp = t >> 5, lane = t & 31;
    for (int i = warp; i < nc; i += 4) {
        int c = scols[i];
        const float* kr = g_qkv + (size_t)(b * SEQ + c) * (3 * DMODEL) + DMODEL + h * HDIM;
        float p = qs[lane] * kr[lane] + qs[lane + 32] * kr[lane + 32];
        #pragma unroll
        for (int o = 16; o; o >>= 1) p += __shfl_down_sync(0xffffffffu, p, o);
        if (lane == 0)
            wgt[i] = 3.0f * (p * 0.125f) + g_pen[q * MAXC + i];
    }
    __syncthreads();

    float lm = -FLT_MAX;
    for (int i = t; i < nc; i += 128) lm = fmaxf(lm, wgt[i]);
    sred[t] = lm; __syncthreads();
    #pragma unroll
    for (int s2 = 64; s2; s2 >>= 1) {
        if (t < s2) sred[t] = fmaxf(sred[t], sred[t + s2]);
        __syncthreads();
    }
    float mx = sred[0];
    __syncthreads();

    float ls = 0.0f;
    for (int i = t; i < nc; i += 128) {
        float e = expf(wgt[i] - mx);
        wgt[i] = e;
        ls += e;
    }
    sred[t] = ls; __syncthreads();
    #pragma unroll
    for (int s2 = 64; s2; s2 >>= 1) {
        if (t < s2) sred[t] += sred[t + s2];
        __syncthreads();
    }
    float inv = 1.0f / sred[0];
    __syncthreads();

    int half = t >> 6, d = t & 63;
    float acc = 0.0f;
    for (int i = half; i < nc; i += 2) {
        int c = scols[i];
        acc += wgt[i] * g_qkv[(size_t)(b * SEQ + c) * (3 * DMODEL) + 2 * DMODEL + h * HDIM + d];
    }
    sred[t] = acc; __syncthreads();
    if (half == 0) {
        float o = (acc + sred[64 + d]) * inv;
        g_attn[(size_t)(b * SEQ + q) * DMODEL + h * HDIM + d] = o;
    }
}

// ---------------- launch ----------------
extern "C" void kernel_launch(void* const* d_in, const int* in_sizes, int n_in,
                              void* d_out, int out_size) {
    const float* x        = (const float*)d_in[0];
    const float* w_qkv    = (const float*)d_in[1];
    const float* w_out    = (const float*)d_in[2];
    const float* ln_gamma = (const float*)d_in[3];
    const float* ln_beta  = (const float*)d_in[4];
    const int*   rand_idx = (const int*)d_in[5];
    float* out = (float*)d_out;

    void *p_xn, *p_qkv, *p_attn, *p_a2, *p_wq2, *p_wo2;
    cudaGetSymbolAddress(&p_xn,   g_xn);
    cudaGetSymbolAddress(&p_qkv,  g_qkv);
    cudaGetSymbolAddress(&p_attn, g_attn);
    cudaGetSymbolAddress(&p_a2,   g_a2);
    cudaGetSymbolAddress(&p_wq2,  g_wq2);
    cudaGetSymbolAddress(&p_wo2,  g_wo2);

    cudaFuncSetAttribute(gemm_mma<0>, cudaFuncAttributeMaxDynamicSharedMemorySize, GSMEM);
    cudaFuncSetAttribute(gemm_mma<1>, cudaFuncAttributeMaxDynamicSharedMemorySize, GSMEM);

    // 1) layernorm + sparse col lists
    ln_kernel<<<NROWS, 256>>>(x, ln_gamma, ln_beta);
    build_cols<<<(SEQ + 127) / 128, 128>>>(rand_idx);

    // 2) bf16-split conversions
    conv_act<<<(NROWS * DMODEL + 255) / 256, 256>>>((const float*)p_xn,
                                                    (__nv_bfloat16*)p_a2, NROWS * DMODEL);
    conv_w<<<dim3(3 * DMODEL / 32, DMODEL / 32), dim3(32, 8)>>>(w_qkv,
                                                    (__nv_bfloat16*)p_wq2, 3 * DMODEL);
    conv_w<<<dim3(DMODEL / 32, DMODEL / 32), dim3(32, 8)>>>(w_out,
                                                    (__nv_bfloat16*)p_wo2, DMODEL);

    // 3) QKV projection (HMMA): [4096 x 3072] = A2 @ Wq2^T
    gemm_mma<0><<<dim3(3 * DMODEL / 128, NROWS / 128), 256, GSMEM>>>(
        (const __nv_bfloat16*)p_a2, (const __nv_bfloat16*)p_wq2,
        (float*)p_qkv, nullptr, 3 * DMODEL);

    // 4) sparse attention
    attn_sparse<<<dim3(SEQ, NHEADS, BATCH), 128>>>();

    // 5) out projection + residual (HMMA)
    conv_act<<<(NROWS * DMODEL + 255) / 256, 256>>>((const float*)p_attn,
                                                    (__nv_bfloat16*)p_a2, NROWS * DMODEL);
    gemm_mma<1><<<dim3(DMODEL / 128, NROWS / 128), 256, GSMEM>>>(
        (const __nv_bfloat16*)p_a2, (const __nv_bfloat16*)p_wo2,
        out, x, DMODEL);
}

// round 8
// speedup vs baseline: 1.6273x; 1.0817x over previous
#include <cuda_runtime.h>
#include <cuda_bf16.h>
#include <float.h>
#include <stdint.h>

// ---------------- problem constants ----------------
#define BATCH     2
#define SEQ       2048
#define DMODEL    1024
#define NHEADS    16
#define HDIM      64
#define WINDOW    64
#define GTOK      4
#define RTOK      32
#define NROWS     (BATCH*SEQ)      // 4096
#define MAXC      112
#define NEGF      (-1000000000.0f)
#define LNEPS     1e-5f
#define KK2       (3*DMODEL)       // 3072: [hi|hi|lo] x [hi;lo;hi] concat-K
#define NCH       (KK2/64)         // 48 k-chunks of 64 bf16

#define TQ        16               // q-tile per attention block
#define WROWS     (WINDOW + TQ)    // 80 window rows
#define KSTR      68               // padded float stride for window K/V

// ---------------- scratch (static device memory) ----------------
__device__ float        g_qkv [NROWS * 3 * DMODEL];
__device__ __nv_bfloat16 g_a2 [NROWS * KK2];          // split activations (reused)
__device__ __nv_bfloat16 g_wq2[3*DMODEL * KK2];       // w_qkv^T split
__device__ __nv_bfloat16 g_wo2[DMODEL   * KK2];       // w_out^T split
__device__ int   g_cols[SEQ * MAXC];
__device__ float g_pen [SEQ * MAXC];
__device__ int   g_ncols[SEQ];

// ---------------- PTX helpers ----------------
__device__ __forceinline__ uint32_t smem_u32(const void* p) {
    uint32_t a;
    asm("{ .reg .u64 t; cvta.to.shared.u64 t, %1; cvt.u32.u64 %0, t; }" : "=r"(a) : "l"(p));
    return a;
}
__device__ __forceinline__ void cpasync16(uint32_t dst, const void* src) {
    asm volatile("cp.async.cg.shared.global [%0], [%1], 16;" :: "r"(dst), "l"(src));
}
__device__ __forceinline__ void ldm_x4(uint32_t* r, uint32_t addr) {
    asm volatile("ldmatrix.sync.aligned.m8n8.x4.shared.b16 {%0,%1,%2,%3}, [%4];"
                 : "=r"(r[0]), "=r"(r[1]), "=r"(r[2]), "=r"(r[3]) : "r"(addr));
}
__device__ __forceinline__ void mma16816(float* c, const uint32_t* a,
                                         uint32_t b0, uint32_t b1) {
    asm volatile("mma.sync.aligned.m16n8k16.row.col.f32.bf16.bf16.f32 "
                 "{%0,%1,%2,%3}, {%4,%5,%6,%7}, {%8,%9}, {%0,%1,%2,%3};"
                 : "+f"(c[0]), "+f"(c[1]), "+f"(c[2]), "+f"(c[3])
                 : "r"(a[0]), "r"(a[1]), "r"(a[2]), "r"(a[3]), "r"(b0), "r"(b1));
}
#define SMEM_SWIZZLE_128B(o) ((o) ^ (((o) >> 3) & 0x70))

// ---------------- layernorm (fused bf16 hi/lo split) ----------------
// writes a2 row: [hi(1024) | hi(1024) | lo(1024)]
__global__ __launch_bounds__(256) void ln_kernel(const float* __restrict__ x,
                                                 const float* __restrict__ gamma,
                                                 const float* __restrict__ beta,
                                                 __nv_bfloat16* __restrict__ a2) {
    int row = blockIdx.x;
    const float4* xr = (const float4*)(x + (size_t)row * DMODEL);
    int t = threadIdx.x;
    float4 v = xr[t];

    __shared__ float sh[8];
    __shared__ float bc;
    int lane = t & 31, warp = t >> 5;

    float s = v.x + v.y + v.z + v.w;
    #pragma unroll
    for (int o = 16; o; o >>= 1) s += __shfl_down_sync(0xffffffffu, s, o);
    if (lane == 0) sh[warp] = s;
    __syncthreads();
    if (t == 0) {
        float tot = 0;
        #pragma unroll
        for (int i = 0; i < 8; i++) tot += sh[i];
        bc = tot * (1.0f / DMODEL);
    }
    __syncthreads();
    float mu = bc;
    __syncthreads();

    float dx = v.x - mu, dy = v.y - mu, dz = v.z - mu, dw = v.w - mu;
    float sq = dx*dx + dy*dy + dz*dz + dw*dw;
    #pragma unroll
    for (int o = 16; o; o >>= 1) sq += __shfl_down_sync(0xffffffffu, sq, o);
    if (lane == 0) sh[warp] = sq;
    __syncthreads();
    if (t == 0) {
        float tot = 0;
        #pragma unroll
        for (int i = 0; i < 8; i++) tot += sh[i];
        bc = rsqrtf(tot * (1.0f / DMODEL) + LNEPS);
    }
    __syncthreads();
    float inv = bc;

    const float4 g = ((const float4*)gamma)[t];
    const float4 b = ((const float4*)beta)[t];
    float r0 = dx * inv * g.x + b.x;
    float r1 = dy * inv * g.y + b.y;
    float r2 = dz * inv * g.z + b.z;
    float r3 = dw * inv * g.w + b.w;

    __nv_bfloat16 h0 = __float2bfloat16(r0), h1 = __float2bfloat16(r1);
    __nv_bfloat16 h2 = __float2bfloat16(r2), h3 = __float2bfloat16(r3);
    __nv_bfloat162 hA; hA.x = h0; hA.y = h1;
    __nv_bfloat162 hB; hB.x = h2; hB.y = h3;
    __nv_bfloat162 lA, lB;
    lA.x = __float2bfloat16(r0 - __bfloat162float(h0));
    lA.y = __float2bfloat16(r1 - __bfloat162float(h1));
    lB.x = __float2bfloat16(r2 - __bfloat162float(h2));
    lB.y = __float2bfloat16(r3 - __bfloat162float(h3));

    size_t rb = (size_t)row * KK2;
    int col = t * 4;
    *(__nv_bfloat162*)(a2 + rb + col)                 = hA;
    *(__nv_bfloat162*)(a2 + rb + col + 2)             = hB;
    *(__nv_bfloat162*)(a2 + rb + DMODEL + col)        = hA;
    *(__nv_bfloat162*)(a2 + rb + DMODEL + col + 2)    = hB;
    *(__nv_bfloat162*)(a2 + rb + 2*DMODEL + col)      = lA;
    *(__nv_bfloat162*)(a2 + rb + 2*DMODEL + col + 2)  = lB;
}

// ---------------- per-row sparse column list + penalties ----------------
__global__ void build_cols(const int* __restrict__ rand_idx) {
    int q = blockIdx.x * blockDim.x + threadIdx.x;
    if (q >= SEQ) return;
    int*   cols = g_cols + q * MAXC;
    float* pen  = g_pen  + q * MAXC;
    const int* ri = rand_idx + q * RTOK;

    int lo = q - WINDOW; if (lo < 0) lo = 0;
    int n = 0;
    for (int c = lo; c <= q; c++) cols[n++] = c;
    int wend = n;

    #pragma unroll
    for (int gi = 0; gi < 2 * GTOK; gi++) {
        int gc = (gi < GTOK) ? gi : (SEQ - 2 * GTOK + gi);
        if (gc <= q && gc < lo) cols[n++] = gc;
    }
    for (int j = 0; j < RTOK; j++) {
        int c = ri[j];
        if (c > q || c >= lo) continue;
        bool dup = false;
        for (int m = wend; m < n; m++) if (cols[m] == c) { dup = true; break; }
        if (!dup) cols[n++] = c;
    }
    g_ncols[q] = n;

    for (int i = 0; i < n; i++) {
        int c = cols[i];
        int s = (c >= lo) ? 1 : 0;
        if (c < GTOK || c >= SEQ - GTOK) s++;
        for (int j = 0; j < RTOK; j++) if (ri[j] == c) { s++; break; }
        pen[i] = (float)(3 - s) * NEGF;
    }
}

// ---------------- bf16 split + transpose: weights ----------------
__global__ __launch_bounds__(256) void conv_w(const float* __restrict__ w,
                                              __nv_bfloat16* __restrict__ wt2,
                                              int Nw) {
    __shared__ float t[32][33];
    int tx = threadIdx.x, ty = threadIdx.y;       // blockDim (32,8)
    int n0 = blockIdx.x * 32, k0 = blockIdx.y * 32;
    #pragma unroll
    for (int r = 0; r < 4; r++)
        t[ty + r * 8][tx] = w[(size_t)(k0 + ty + r * 8) * Nw + n0 + tx];
    __syncthreads();
    #pragma unroll
    for (int r = 0; r < 4; r++) {
        int n = n0 + ty + r * 8;
        int k = k0 + tx;
        float f = t[tx][ty + r * 8];
        __nv_bfloat16 hi = __float2bfloat16(f);
        __nv_bfloat16 lo = __float2bfloat16(f - __bfloat162float(hi));
        size_t b = (size_t)n * KK2;
        wt2[b + k] = hi;
        wt2[b + DMODEL + k] = lo;
        wt2[b + 2 * DMODEL + k] = hi;
    }
}

// ---------------- bf16 HMMA GEMM (unchanged from R6) ----------------
#define GSTAGE 32768
#define GSMEM  (4 * GSTAGE)

template<int RES>
__global__ __launch_bounds__(256, 1) void gemm_mma(const __nv_bfloat16* __restrict__ A,
                                                   const __nv_bfloat16* __restrict__ Bt,
                                                   float* __restrict__ C,
                                                   const float* __restrict__ res,
                                                   int N) {
    extern __shared__ char smem[];
    uint32_t sb = smem_u32(smem);
    const int tid = threadIdx.x, wid = tid >> 5, lid = tid & 31;
    const int brow = blockIdx.y * 128, bcol = blockIdx.x * 128;
    const int wm = wid & 1, wn = wid >> 1;

    auto issue = [&](int c) {
        uint32_t abase = sb + (c & 3) * GSTAGE;
        uint32_t bbase = abase + 16384;
        int k0 = c * 64;
        #pragma unroll
        for (int i = 0; i < 4; i++) {
            int ca = tid + i * 256;
            int row = ca >> 3, seg = ca & 7;
            uint32_t off = SMEM_SWIZZLE_128B((uint32_t)(row * 128 + seg * 16));
            cpasync16(abase + off, A  + (size_t)(brow + row) * KK2 + k0 + seg * 8);
            cpasync16(bbase + off, Bt + (size_t)(bcol + row) * KK2 + k0 + seg * 8);
        }
        asm volatile("cp.async.commit_group;");
    };

    float acc[4][4][4];
    #pragma unroll
    for (int i = 0; i < 4; i++)
        #pragma unroll
        for (int j = 0; j < 4; j++)
            #pragma unroll
            for (int k = 0; k < 4; k++) acc[i][j][k] = 0.0f;

    const int xa   = (lid & 7) << 4;
    const int arow = wm * 64 + (lid & 15);
    const int akhi = (lid >> 4) * 16;
    const int bnrow = wn * 32 + (lid & 7) + ((lid >> 4) << 3);
    const int bkhi  = ((lid >> 3) & 1) * 16;

    issue(0); issue(1); issue(2); issue(3);

    for (int c = 0; c < NCH; c++) {
        int pend = NCH - 1 - c;
        if (pend >= 3)      asm volatile("cp.async.wait_group 3;" ::: "memory");
        else if (pend == 2) asm volatile("cp.async.wait_group 2;" ::: "memory");
        else if (pend == 1) asm volatile("cp.async.wait_group 1;" ::: "memory");
        else                asm volatile("cp.async.wait_group 0;" ::: "memory");
        __syncthreads();

        uint32_t abase = sb + (c & 3) * GSTAGE;
        uint32_t bbase = abase + 16384;

        #pragma unroll
        for (int ks = 0; ks < 4; ks++) {
            uint32_t a[4][4], b[2][4];
            int kb = ks * 32;
            #pragma unroll
            for (int mt = 0; mt < 4; mt++)
                ldm_x4(a[mt], abase + (arow + mt * 16) * 128 + ((kb + akhi) ^ xa));
            #pragma unroll
            for (int nt2 = 0; nt2 < 2; nt2++)
                ldm_x4(b[nt2], bbase + (bnrow + nt2 * 16) * 128 + ((kb + bkhi) ^ xa));
            #pragma unroll
            for (int mt = 0; mt < 4; mt++)
                #pragma unroll
                for (int nt = 0; nt < 4; nt++)
                    mma16816(acc[mt][nt], a[mt],
                             b[nt >> 1][(nt & 1) * 2], b[nt >> 1][(nt & 1) * 2 + 1]);
        }
        __syncthreads();
        if (c + 4 < NCH) issue(c + 4);
    }

    const int g = lid >> 2, tg = lid & 3;
    #pragma unroll
    for (int mt = 0; mt < 4; mt++) {
        int r0 = brow + wm * 64 + mt * 16 + g;
        #pragma unroll
        for (int nt = 0; nt < 4; nt++) {
            int cI = bcol + wn * 32 + nt * 8 + tg * 2;
            float2 v0 = make_float2(acc[mt][nt][0], acc[mt][nt][1]);
            float2 v1 = make_float2(acc[mt][nt][2], acc[mt][nt][3]);
            if (RES) {
                float2 r0v = *(const float2*)(res + (size_t)r0 * N + cI);
                float2 r1v = *(const float2*)(res + (size_t)(r0 + 8) * N + cI);
                v0.x += r0v.x; v0.y += r0v.y;
                v1.x += r1v.x; v1.y += r1v.y;
            }
            *(float2*)(C + (size_t)r0 * N + cI) = v0;
            *(float2*)(C + (size_t)(r0 + 8) * N + cI) = v1;
        }
    }
}

// ---------------- sparse attention v2: q-tiled, window K/V in smem ----------
// block = (q-tile of TQ, head, batch), 256 threads (8 warps, 2 q's per warp).
// Output written directly as split bf16 into g_a2 ([hi|hi|lo] layout).
#define ASM_KW    0                               // floats
#define ASM_VW    (WROWS * KSTR)
#define ASM_QS    (2 * WROWS * KSTR)
#define ASM_WB    (ASM_QS + TQ * 64)
#define ASM_PEN   (ASM_WB + 8 * MAXC)
#define ASM_COLS  (ASM_PEN + TQ * MAXC)           // ints from here
#define ASM_NCOL  (ASM_COLS + TQ * MAXC)
#define ATT_SMEM  ((ASM_NCOL + TQ) * 4)

__global__ __launch_bounds__(256, 1) void attn_sparse2(__nv_bfloat16* __restrict__ a2) {
    extern __shared__ float sm[];
    float* kw  = sm + ASM_KW;
    float* vw  = sm + ASM_VW;
    float* qs  = sm + ASM_QS;
    float* wb  = sm + ASM_WB;
    float* pen = sm + ASM_PEN;
    int*  cols = (int*)(sm + ASM_COLS);
    int*  ncol = (int*)(sm + ASM_NCOL);

    int q0 = blockIdx.x * TQ;
    int h  = blockIdx.y, b = blockIdx.z;
    int lo0 = q0 - WINDOW; if (lo0 < 0) lo0 = 0;
    int nrows = q0 + TQ - lo0;                 // <= 80
    int tid = threadIdx.x;

    const float* qkvb = g_qkv + (size_t)b * SEQ * KK2;

    // window K/V rows -> smem (padded stride)
    for (int i = tid; i < nrows * 16; i += 256) {
        int r = i >> 4, d4 = (i & 15) * 4;
        const float* src = qkvb + (size_t)(lo0 + r) * KK2 + h * HDIM + d4;
        *(float4*)(kw + r * KSTR + d4) = *(const float4*)(src + DMODEL);
        *(float4*)(vw + r * KSTR + d4) = *(const float4*)(src + 2 * DMODEL);
    }
    // Q rows
    for (int i = tid; i < TQ * 16; i += 256) {
        int r = i >> 4, d4 = (i & 15) * 4;
        *(float4*)(qs + r * 64 + d4) =
            *(const float4*)(qkvb + (size_t)(q0 + r) * KK2 + h * HDIM + d4);
    }
    // col lists + penalties
    for (int i = tid; i < TQ * MAXC; i += 256) {
        int r = i / MAXC, j = i - r * MAXC;
        cols[i] = g_cols[(q0 + r) * MAXC + j];
        pen[i]  = g_pen [(q0 + r) * MAXC + j];
    }
    if (tid < TQ) ncol[tid] = g_ncols[q0 + tid];
    __syncthreads();

    int wid = tid >> 5, lane = tid & 31;

    for (int qi = wid; qi < TQ; qi += 8) {
        int q = q0 + qi;
        int nc = ncol[qi];
        int lo = q - WINDOW; if (lo < 0) lo = 0;
        int wend = q - lo + 1;
        float* w = wb + wid * MAXC;
        const float* qrow = qs + qi * 64;
        const float* prow = pen + qi * MAXC;
        const int*   crow = cols + qi * MAXC;

        // phase A: window columns (contiguous lo..q), dots from smem
        for (int i = lane; i < wend; i += 32) {
            const float* kr = kw + (lo + i - lo0) * KSTR;
            float p = 0.0f;
            #pragma unroll
            for (int d4 = 0; d4 < 64; d4 += 4) {
                float4 k4 = *(const float4*)(kr + d4);
                float4 q4 = *(const float4*)(qrow + d4);
                p += k4.x*q4.x + k4.y*q4.y + k4.z*q4.z + k4.w*q4.w;
            }
            w[i] = 3.0f * (p * 0.125f) + prow[i];
        }
        // phase B: appended (global/random) columns, warp-per-column coalesced
        for (int i = wend; i < nc; i++) {
            int c = crow[i];
            const float* kr = qkvb + (size_t)c * KK2 + DMODEL + h * HDIM;
            float p = qrow[lane] * kr[lane] + qrow[lane + 32] * kr[lane + 32];
            #pragma unroll
            for (int o = 16; o; o >>= 1) p += __shfl_down_sync(0xffffffffu, p, o);
            if (lane == 0) w[i] = 3.0f * (p * 0.125f) + prow[i];
        }
        __syncwarp();

        // softmax (warp-local)
        float lm = -FLT_MAX;
        for (int i = lane; i < nc; i += 32) lm = fmaxf(lm, w[i]);
        #pragma unroll
        for (int o = 16; o; o >>= 1) lm = fmaxf(lm, __shfl_xor_sync(0xffffffffu, lm, o));
        float ls = 0.0f;
        for (int i = lane; i < nc; i += 32) {
            float e = expf(w[i] - lm);
            w[i] = e;
            ls += e;
        }
        #pragma unroll
        for (int o = 16; o; o >>= 1) ls += __shfl_xor_sync(0xffffffffu, ls, o);
        float inv = 1.0f / ls;
        __syncwarp();

        // phase V: lane owns dims lane and lane+32
        float a0 = 0.0f, a1 = 0.0f;
        for (int i = 0; i < wend; i++) {
            float wi = w[i];
            const float* vr = vw + (lo + i - lo0) * KSTR;
            a0 += wi * vr[lane];
            a1 += wi * vr[lane + 32];
        }
        for (int i = wend; i < nc; i++) {
            float wi = w[i];
            const float* vr = qkvb + (size_t)crow[i] * KK2 + 2 * DMODEL + h * HDIM;
            a0 += wi * vr[lane];
            a1 += wi * vr[lane + 32];
        }
        a0 *= inv; a1 *= inv;

        // fused bf16 hi/lo split write into a2 [hi|hi|lo]
        size_t rb = (size_t)(b * SEQ + q) * KK2;
        int col0 = h * HDIM + lane;
        __nv_bfloat16 h0 = __float2bfloat16(a0);
        __nv_bfloat16 h1 = __float2bfloat16(a1);
        __nv_bfloat16 l0 = __float2bfloat16(a0 - __bfloat162float(h0));
        __nv_bfloat16 l1 = __float2bfloat16(a1 - __bfloat162float(h1));
        a2[rb + col0]                    = h0;
        a2[rb + col0 + 32]               = h1;
        a2[rb + DMODEL + col0]           = h0;
        a2[rb + DMODEL + col0 + 32]      = h1;
        a2[rb + 2 * DMODEL + col0]       = l0;
        a2[rb + 2 * DMODEL + col0 + 32]  = l1;
    }
}

// ---------------- launch ----------------
extern "C" void kernel_launch(void* const* d_in, const int* in_sizes, int n_in,
                              void* d_out, int out_size) {
    const float* x        = (const float*)d_in[0];
    const float* w_qkv    = (const float*)d_in[1];
    const float* w_out    = (const float*)d_in[2];
    const float* ln_gamma = (const float*)d_in[3];
    const float* ln_beta  = (const float*)d_in[4];
    const int*   rand_idx = (const int*)d_in[5];
    float* out = (float*)d_out;

    void *p_qkv, *p_a2, *p_wq2, *p_wo2;
    cudaGetSymbolAddress(&p_qkv,  g_qkv);
    cudaGetSymbolAddress(&p_a2,   g_a2);
    cudaGetSymbolAddress(&p_wq2,  g_wq2);
    cudaGetSymbolAddress(&p_wo2,  g_wo2);

    cudaFuncSetAttribute(gemm_mma<0>, cudaFuncAttributeMaxDynamicSharedMemorySize, GSMEM);
    cudaFuncSetAttribute(gemm_mma<1>, cudaFuncAttributeMaxDynamicSharedMemorySize, GSMEM);
    cudaFuncSetAttribute(attn_sparse2, cudaFuncAttributeMaxDynamicSharedMemorySize, ATT_SMEM);

    // 1) layernorm with fused bf16 split -> a2
    ln_kernel<<<NROWS, 256>>>(x, ln_gamma, ln_beta, (__nv_bfloat16*)p_a2);
    build_cols<<<(SEQ + 127) / 128, 128>>>(rand_idx);

    // 2) weight splits
    conv_w<<<dim3(3 * DMODEL / 32, DMODEL / 32), dim3(32, 8)>>>(w_qkv,
                                                    (__nv_bfloat16*)p_wq2, 3 * DMODEL);
    conv_w<<<dim3(DMODEL / 32, DMODEL / 32), dim3(32, 8)>>>(w_out,
                                                    (__nv_bfloat16*)p_wo2, DMODEL);

    // 3) QKV projection (HMMA): [4096 x 3072]
    gemm_mma<0><<<dim3(3 * DMODEL / 128, NROWS / 128), 256, GSMEM>>>(
        (const __nv_bfloat16*)p_a2, (const __nv_bfloat16*)p_wq2,
        (float*)p_qkv, nullptr, 3 * DMODEL);

    // 4) sparse attention (q-tiled) with fused split write -> a2
    attn_sparse2<<<dim3(SEQ / TQ, NHEADS, BATCH), 256, ATT_SMEM>>>(
        (__nv_bfloat16*)p_a2);

    // 5) out projection + residual (HMMA)
    gemm_mma<1><<<dim3(DMODEL / 128, NROWS / 128), 256, GSMEM>>>(
        (const __nv_bfloat16*)p_a2, (const __nv_bfloat16*)p_wo2,
        out, x, DMODEL);
}

// round 9
// speedup vs baseline: 1.9147x; 1.1766x over previous
#include <cuda_runtime.h>
#include <cuda_fp16.h>
#include <float.h>
#include <stdint.h>

// ---------------- problem constants ----------------
#define BATCH     2
#define SEQ       2048
#define DMODEL    1024
#define NHEADS    16
#define HDIM      64
#define WINDOW    64
#define GTOK      4
#define RTOK      32
#define NROWS     (BATCH*SEQ)      // 4096
#define MAXC      112
#define NEGF      (-1000000000.0f)
#define LNEPS     1e-5f
#define QW        (3*DMODEL)       // qkv row width (3072 floats)
#define KCAT      (2*DMODEL)       // 2048: fp16 2-term concat-K [hi|lo] x [hi;hi]
#define NCH       (KCAT/64)        // 32 k-chunks of 64 fp16

#define TQ        16               // q-tile per attention block
#define WROWS     (WINDOW + TQ)    // 80 window rows
#define KSTR      68               // padded float stride for window K/V

// ---------------- scratch (static device memory) ----------------
__device__ float  g_qkv [NROWS * QW];
__device__ __half g_a2 [NROWS * KCAT];          // split activations (reused)
__device__ __half g_wq2[3*DMODEL * KCAT];       // w_qkv^T split  [N=3072][K'=2048]
__device__ __half g_wo2[DMODEL   * KCAT];       // w_out^T split  [N=1024][K'=2048]
__device__ int   g_cols[SEQ * MAXC];
__device__ float g_pen [SEQ * MAXC];
__device__ int   g_ncols[SEQ];

// ---------------- PTX helpers ----------------
__device__ __forceinline__ uint32_t smem_u32(const void* p) {
    uint32_t a;
    asm("{ .reg .u64 t; cvta.to.shared.u64 t, %1; cvt.u32.u64 %0, t; }" : "=r"(a) : "l"(p));
    return a;
}
__device__ __forceinline__ void cpasync16(uint32_t dst, const void* src) {
    asm volatile("cp.async.cg.shared.global [%0], [%1], 16;" :: "r"(dst), "l"(src));
}
__device__ __forceinline__ void ldm_x4(uint32_t* r, uint32_t addr) {
    asm volatile("ldmatrix.sync.aligned.m8n8.x4.shared.b16 {%0,%1,%2,%3}, [%4];"
                 : "=r"(r[0]), "=r"(r[1]), "=r"(r[2]), "=r"(r[3]) : "r"(addr));
}
__device__ __forceinline__ void mma16816(float* c, const uint32_t* a,
                                         uint32_t b0, uint32_t b1) {
    asm volatile("mma.sync.aligned.m16n8k16.row.col.f32.f16.f16.f32 "
                 "{%0,%1,%2,%3}, {%4,%5,%6,%7}, {%8,%9}, {%0,%1,%2,%3};"
                 : "+f"(c[0]), "+f"(c[1]), "+f"(c[2]), "+f"(c[3])
                 : "r"(a[0]), "r"(a[1]), "r"(a[2]), "r"(a[3]), "r"(b0), "r"(b1));
}
#define SMEM_SWIZZLE_128B(o) ((o) ^ (((o) >> 3) & 0x70))

// ---------------- layernorm (fused fp16 hi/lo split) ----------------
// writes a2 row: [hi(1024) | lo(1024)]
__global__ __launch_bounds__(256) void ln_kernel(const float* __restrict__ x,
                                                 const float* __restrict__ gamma,
                                                 const float* __restrict__ beta,
                                                 __half* __restrict__ a2) {
    int row = blockIdx.x;
    const float4* xr = (const float4*)(x + (size_t)row * DMODEL);
    int t = threadIdx.x;
    float4 v = xr[t];

    __shared__ float sh[8];
    __shared__ float bc;
    int lane = t & 31, warp = t >> 5;

    float s = v.x + v.y + v.z + v.w;
    #pragma unroll
    for (int o = 16; o; o >>= 1) s += __shfl_down_sync(0xffffffffu, s, o);
    if (lane == 0) sh[warp] = s;
    __syncthreads();
    if (t == 0) {
        float tot = 0;
        #pragma unroll
        for (int i = 0; i < 8; i++) tot += sh[i];
        bc = tot * (1.0f / DMODEL);
    }
    __syncthreads();
    float mu = bc;
    __syncthreads();

    float dx = v.x - mu, dy = v.y - mu, dz = v.z - mu, dw = v.w - mu;
    float sq = dx*dx + dy*dy + dz*dz + dw*dw;
    #pragma unroll
    for (int o = 16; o; o >>= 1) sq += __shfl_down_sync(0xffffffffu, sq, o);
    if (lane == 0) sh[warp] = sq;
    __syncthreads();
    if (t == 0) {
        float tot = 0;
        #pragma unroll
        for (int i = 0; i < 8; i++) tot += sh[i];
        bc = rsqrtf(tot * (1.0f / DMODEL) + LNEPS);
    }
    __syncthreads();
    float inv = bc;

    const float4 g = ((const float4*)gamma)[t];
    const float4 b = ((const float4*)beta)[t];
    float r0 = dx * inv * g.x + b.x;
    float r1 = dy * inv * g.y + b.y;
    float r2 = dz * inv * g.z + b.z;
    float r3 = dw * inv * g.w + b.w;

    __half h0 = __float2half(r0), h1 = __float2half(r1);
    __half h2 = __float2half(r2), h3 = __float2half(r3);
    __half2 hA = __halves2half2(h0, h1);
    __half2 hB = __halves2half2(h2, h3);
    __half2 lA = __halves2half2(__float2half(r0 - __half2float(h0)),
                                __float2half(r1 - __half2float(h1)));
    __half2 lB = __halves2half2(__float2half(r2 - __half2float(h2)),
                                __float2half(r3 - __half2float(h3)));

    size_t rb = (size_t)row * KCAT;
    int col = t * 4;
    *(__half2*)(a2 + rb + col)              = hA;
    *(__half2*)(a2 + rb + col + 2)          = hB;
    *(__half2*)(a2 + rb + DMODEL + col)     = lA;
    *(__half2*)(a2 + rb + DMODEL + col + 2) = lB;
}

// ---------------- per-row sparse column list + penalties ----------------
__global__ void build_cols(const int* __restrict__ rand_idx) {
    int q = blockIdx.x * blockDim.x + threadIdx.x;
    if (q >= SEQ) return;
    int*   cols = g_cols + q * MAXC;
    float* pen  = g_pen  + q * MAXC;
    const int* ri = rand_idx + q * RTOK;

    int lo = q - WINDOW; if (lo < 0) lo = 0;
    int n = 0;
    for (int c = lo; c <= q; c++) cols[n++] = c;
    int wend = n;

    #pragma unroll
    for (int gi = 0; gi < 2 * GTOK; gi++) {
        int gc = (gi < GTOK) ? gi : (SEQ - 2 * GTOK + gi);
        if (gc <= q && gc < lo) cols[n++] = gc;
    }
    for (int j = 0; j < RTOK; j++) {
        int c = ri[j];
        if (c > q || c >= lo) continue;
        bool dup = false;
        for (int m = wend; m < n; m++) if (cols[m] == c) { dup = true; break; }
        if (!dup) cols[n++] = c;
    }
    g_ncols[q] = n;

    for (int i = 0; i < n; i++) {
        int c = cols[i];
        int s = (c >= lo) ? 1 : 0;
        if (c < GTOK || c >= SEQ - GTOK) s++;
        for (int j = 0; j < RTOK; j++) if (ri[j] == c) { s++; break; }
        pen[i] = (float)(3 - s) * NEGF;
    }
}

// ---------------- fp16 transpose: weights (hi duplicated) ----------------
// w [1024, Nw] f32 -> wt2 [Nw, 2048] fp16, row n: [hi(w[:,n]) | hi(w[:,n])]
__global__ __launch_bounds__(256) void conv_w(const float* __restrict__ w,
                                              __half* __restrict__ wt2,
                                              int Nw) {
    __shared__ float t[32][33];
    int tx = threadIdx.x, ty = threadIdx.y;       // blockDim (32,8)
    int n0 = blockIdx.x * 32, k0 = blockIdx.y * 32;
    #pragma unroll
    for (int r = 0; r < 4; r++)
        t[ty + r * 8][tx] = w[(size_t)(k0 + ty + r * 8) * Nw + n0 + tx];
    __syncthreads();
    #pragma unroll
    for (int r = 0; r < 4; r++) {
        int n = n0 + ty + r * 8;
        int k = k0 + tx;
        __half hi = __float2half(t[tx][ty + r * 8]);
        size_t b = (size_t)n * KCAT;
        wt2[b + k] = hi;
        wt2[b + DMODEL + k] = hi;
    }
}

// ---------------- fp16 HMMA GEMM: C[M,N] = A2[M,K'] @ Bt[N,K']^T (+res) ------
// 128x128 block tile, BK=64, 256 threads (8 warps), warp tile 64x32.
// 4-stage cp.async pipeline, SW128-swizzled SMEM, ldmatrix + mma.sync m16n8k16.
#define GSTAGE 32768
#define GSMEM  (4 * GSTAGE)

template<int RES>
__global__ __launch_bounds__(256, 1) void gemm_mma(const __half* __restrict__ A,
                                                   const __half* __restrict__ Bt,
                                                   float* __restrict__ C,
                                                   const float* __restrict__ res,
                                                   int N) {
    extern __shared__ char smem[];
    uint32_t sb = smem_u32(smem);
    const int tid = threadIdx.x, wid = tid >> 5, lid = tid & 31;
    const int brow = blockIdx.y * 128, bcol = blockIdx.x * 128;
    const int wm = wid & 1, wn = wid >> 1;

    auto issue = [&](int c) {
        uint32_t abase = sb + (c & 3) * GSTAGE;
        uint32_t bbase = abase + 16384;
        int k0 = c * 64;
        #pragma unroll
        for (int i = 0; i < 4; i++) {
            int ca = tid + i * 256;
            int row = ca >> 3, seg = ca & 7;
            uint32_t off = SMEM_SWIZZLE_128B((uint32_t)(row * 128 + seg * 16));
            cpasync16(abase + off, A  + (size_t)(brow + row) * KCAT + k0 + seg * 8);
            cpasync16(bbase + off, Bt + (size_t)(bcol + row) * KCAT + k0 + seg * 8);
        }
        asm volatile("cp.async.commit_group;");
    };

    float acc[4][4][4];
    #pragma unroll
    for (int i = 0; i < 4; i++)
        #pragma unroll
        for (int j = 0; j < 4; j++)
            #pragma unroll
            for (int k = 0; k < 4; k++) acc[i][j][k] = 0.0f;

    const int xa   = (lid & 7) << 4;
    const int arow = wm * 64 + (lid & 15);
    const int akhi = (lid >> 4) * 16;
    const int bnrow = wn * 32 + (lid & 7) + ((lid >> 4) << 3);
    const int bkhi  = ((lid >> 3) & 1) * 16;

    issue(0); issue(1); issue(2); issue(3);

    for (int c = 0; c < NCH; c++) {
        int pend = NCH - 1 - c;
        if (pend >= 3)      asm volatile("cp.async.wait_group 3;" ::: "memory");
        else if (pend == 2) asm volatile("cp.async.wait_group 2;" ::: "memory");
        else if (pend == 1) asm volatile("cp.async.wait_group 1;" ::: "memory");
        else                asm volatile("cp.async.wait_group 0;" ::: "memory");
        __syncthreads();

        uint32_t abase = sb + (c & 3) * GSTAGE;
        uint32_t bbase = abase + 16384;

        #pragma unroll
        for (int ks = 0; ks < 4; ks++) {
            uint32_t a[4][4], b[2][4];
            int kb = ks * 32;
            #pragma unroll
            for (int mt = 0; mt < 4; mt++)
                ldm_x4(a[mt], abase + (arow + mt * 16) * 128 + ((kb + akhi) ^ xa));
            #pragma unroll
            for (int nt2 = 0; nt2 < 2; nt2++)
                ldm_x4(b[nt2], bbase + (bnrow + nt2 * 16) * 128 + ((kb + bkhi) ^ xa));
            #pragma unroll
            for (int mt = 0; mt < 4; mt++)
                #pragma unroll
                for (int nt = 0; nt < 4; nt++)
                    mma16816(acc[mt][nt], a[mt],
                             b[nt >> 1][(nt & 1) * 2], b[nt >> 1][(nt & 1) * 2 + 1]);
        }
        __syncthreads();
        if (c + 4 < NCH) issue(c + 4);
    }

    const int g = lid >> 2, tg = lid & 3;
    #pragma unroll
    for (int mt = 0; mt < 4; mt++) {
        int r0 = brow + wm * 64 + mt * 16 + g;
        #pragma unroll
        for (int nt = 0; nt < 4; nt++) {
            int cI = bcol + wn * 32 + nt * 8 + tg * 2;
            float2 v0 = make_float2(acc[mt][nt][0], acc[mt][nt][1]);
            float2 v1 = make_float2(acc[mt][nt][2], acc[mt][nt][3]);
            if (RES) {
                float2 r0v = *(const float2*)(res + (size_t)r0 * N + cI);
                float2 r1v = *(const float2*)(res + (size_t)(r0 + 8) * N + cI);
                v0.x += r0v.x; v0.y += r0v.y;
                v1.x += r1v.x; v1.y += r1v.y;
            }
            *(float2*)(C + (size_t)r0 * N + cI) = v0;
            *(float2*)(C + (size_t)(r0 + 8) * N + cI) = v1;
        }
    }
}

// ---------------- sparse attention v2: q-tiled, window K/V in smem ----------
#define ASM_KW    0                               // floats
#define ASM_VW    (WROWS * KSTR)
#define ASM_QS    (2 * WROWS * KSTR)
#define ASM_WB    (ASM_QS + TQ * 64)
#define ASM_PEN   (ASM_WB + 8 * MAXC)
#define ASM_COLS  (ASM_PEN + TQ * MAXC)           // ints from here
#define ASM_NCOL  (ASM_COLS + TQ * MAXC)
#define ATT_SMEM  ((ASM_NCOL + TQ) * 4)

__global__ __launch_bounds__(256, 1) void attn_sparse2(__half* __restrict__ a2) {
    extern __shared__ float sm[];
    float* kw  = sm + ASM_KW;
    float* vw  = sm + ASM_VW;
    float* qs  = sm + ASM_QS;
    float* wb  = sm + ASM_WB;
    float* pen = sm + ASM_PEN;
    int*  cols = (int*)(sm + ASM_COLS);
    int*  ncol = (int*)(sm + ASM_NCOL);

    int q0 = blockIdx.x * TQ;
    int h  = blockIdx.y, b = blockIdx.z;
    int lo0 = q0 - WINDOW; if (lo0 < 0) lo0 = 0;
    int nrows = q0 + TQ - lo0;                 // <= 80
    int tid = threadIdx.x;

    const float* qkvb = g_qkv + (size_t)b * SEQ * QW;

    for (int i = tid; i < nrows * 16; i += 256) {
        int r = i >> 4, d4 = (i & 15) * 4;
        const float* src = qkvb + (size_t)(lo0 + r) * QW + h * HDIM + d4;
        *(float4*)(kw + r * KSTR + d4) = *(const float4*)(src + DMODEL);
        *(float4*)(vw + r * KSTR + d4) = *(const float4*)(src + 2 * DMODEL);
    }
    for (int i = tid; i < TQ * 16; i += 256) {
        int r = i >> 4, d4 = (i & 15) * 4;
        *(float4*)(qs + r * 64 + d4) =
            *(const float4*)(qkvb + (size_t)(q0 + r) * QW + h * HDIM + d4);
    }
    for (int i = tid; i < TQ * MAXC; i += 256) {
        int r = i / MAXC, j = i - r * MAXC;
        cols[i] = g_cols[(q0 + r) * MAXC + j];
        pen[i]  = g_pen [(q0 + r) * MAXC + j];
    }
    if (tid < TQ) ncol[tid] = g_ncols[q0 + tid];
    __syncthreads();

    int wid = tid >> 5, lane = tid & 31;

    for (int qi = wid; qi < TQ; qi += 8) {
        int q = q0 + qi;
        int nc = ncol[qi];
        int lo = q - WINDOW; if (lo < 0) lo = 0;
        int wend = q - lo + 1;
        float* w = wb + wid * MAXC;
        const float* qrow = qs + qi * 64;
        const float* prow = pen + qi * MAXC;
        const int*   crow = cols + qi * MAXC;

        for (int i = lane; i < wend; i += 32) {
            const float* kr = kw + (lo + i - lo0) * KSTR;
            float p = 0.0f;
            #pragma unroll
            for (int d4 = 0; d4 < 64; d4 += 4) {
                float4 k4 = *(const float4*)(kr + d4);
                float4 q4 = *(const float4*)(qrow + d4);
                p += k4.x*q4.x + k4.y*q4.y + k4.z*q4.z + k4.w*q4.w;
            }
            w[i] = 3.0f * (p * 0.125f) + prow[i];
        }
        for (int i = wend; i < nc; i++) {
            int c = crow[i];
            const float* kr = qkvb + (size_t)c * QW + DMODEL + h * HDIM;
            float p = qrow[lane] * kr[lane] + qrow[lane + 32] * kr[lane + 32];
            #pragma unroll
            for (int o = 16; o; o >>= 1) p += __shfl_down_sync(0xffffffffu, p, o);
            if (lane == 0) w[i] = 3.0f * (p * 0.125f) + prow[i];
        }
        __syncwarp();

        float lm = -FLT_MAX;
        for (int i = lane; i < nc; i += 32) lm = fmaxf(lm, w[i]);
        #pragma unroll
        for (int o = 16; o; o >>= 1) lm = fmaxf(lm, __shfl_xor_sync(0xffffffffu, lm, o));
        float ls = 0.0f;
        for (int i = lane; i < nc; i += 32) {
            float e = expf(w[i] - lm);
            w[i] = e;
            ls += e;
        }
        #pragma unroll
        for (int o = 16; o; o >>= 1) ls += __shfl_xor_sync(0xffffffffu, ls, o);
        float inv = 1.0f / ls;
        __syncwarp();

        float a0 = 0.0f, a1 = 0.0f;
        for (int i = 0; i < wend; i++) {
            float wi = w[i];
            const float* vr = vw + (lo + i - lo0) * KSTR;
            a0 += wi * vr[lane];
            a1 += wi * vr[lane + 32];
        }
        for (int i = wend; i < nc; i++) {
            float wi = w[i];
            const float* vr = qkvb + (size_t)crow[i] * QW + 2 * DMODEL + h * HDIM;
            a0 += wi * vr[lane];
            a1 += wi * vr[lane + 32];
        }
        a0 *= inv; a1 *= inv;

        // fused fp16 hi/lo split write into a2 [hi|lo]
        size_t rb = (size_t)(b * SEQ + q) * KCAT;
        int col0 = h * HDIM + lane;
        __half h0 = __float2half(a0);
        __half h1 = __float2half(a1);
        a2[rb + col0]                   = h0;
        a2[rb + col0 + 32]              = h1;
        a2[rb + DMODEL + col0]          = __float2half(a0 - __half2float(h0));
        a2[rb + DMODEL + col0 + 32]     = __float2half(a1 - __half2float(h1));
    }
}

// ---------------- launch ----------------
extern "C" void kernel_launch(void* const* d_in, const int* in_sizes, int n_in,
                              void* d_out, int out_size) {
    const float* x        = (const float*)d_in[0];
    const float* w_qkv    = (const float*)d_in[1];
    const float* w_out    = (const float*)d_in[2];
    const float* ln_gamma = (const float*)d_in[3];
    const float* ln_beta  = (const float*)d_in[4];
    const int*   rand_idx = (const int*)d_in[5];
    float* out = (float*)d_out;

    void *p_qkv, *p_a2, *p_wq2, *p_wo2;
    cudaGetSymbolAddress(&p_qkv,  g_qkv);
    cudaGetSymbolAddress(&p_a2,   g_a2);
    cudaGetSymbolAddress(&p_wq2,  g_wq2);
    cudaGetSymbolAddress(&p_wo2,  g_wo2);

    cudaFuncSetAttribute(gemm_mma<0>, cudaFuncAttributeMaxDynamicSharedMemorySize, GSMEM);
    cudaFuncSetAttribute(gemm_mma<1>, cudaFuncAttributeMaxDynamicSharedMemorySize, GSMEM);
    cudaFuncSetAttribute(attn_sparse2, cudaFuncAttributeMaxDynamicSharedMemorySize, ATT_SMEM);

    // 1) layernorm with fused fp16 split -> a2
    ln_kernel<<<NROWS, 256>>>(x, ln_gamma, ln_beta, (__half*)p_a2);
    build_cols<<<(SEQ + 127) / 128, 128>>>(rand_idx);

    // 2) weight transposes (hi duplicated)
    conv_w<<<dim3(3 * DMODEL / 32, DMODEL / 32), dim3(32, 8)>>>(w_qkv,
                                                    (__half*)p_wq2, 3 * DMODEL);
    conv_w<<<dim3(DMODEL / 32, DMODEL / 32), dim3(32, 8)>>>(w_out,
                                                    (__half*)p_wo2, DMODEL);

    // 3) QKV projection (fp16 HMMA): [4096 x 3072]
    gemm_mma<0><<<dim3(3 * DMODEL / 128, NROWS / 128), 256, GSMEM>>>(
        (const __half*)p_a2, (const __half*)p_wq2,
        (float*)p_qkv, nullptr, 3 * DMODEL);

    // 4) sparse attention (q-tiled) with fused split write -> a2
    attn_sparse2<<<dim3(SEQ / TQ, NHEADS, BATCH), 256, ATT_SMEM>>>(
        (__half*)p_a2);

    // 5) out projection + residual (fp16 HMMA)
    gemm_mma<1><<<dim3(DMODEL / 128, NROWS / 128), 256, GSMEM>>>(
        (const __half*)p_a2, (const __half*)p_wo2,
        out, x, DMODEL);
}